// round 6
// baseline (speedup 1.0000x reference)
#include <cuda_runtime.h>

// AttentionBlock fused gate kernel — 256-bit loads (sm_10x LDG.E.256), ILP=2.
// Inputs: xatt[B*L*C], xsaut[B*L*C], W_act[C], b_act[1], W_saut[C], b_saut[1], W2[1], b2[1]
// Output: out[B*L] fp32.  B=64, L=16384, C=64 -> n_pos = 1,048,576 (n_pairs = 524,288).
//
// 8 lanes per position; each lane loads 8 floats (32B, ld.global.nc.v8.f32)
// from each input row for TWO adjacent positions -> 4 independent 256-bit
// loads per thread. 3-level shuffle reduction over the 8-lane group; lane 0
// writes a float2.

#define NEG_SLOPE 0.3f

struct F8 { float r0, r1, r2, r3, r4, r5, r6, r7; };

__device__ __forceinline__ F8 ldg256(const float* p) {
    F8 v;
    asm volatile("ld.global.nc.v8.f32 {%0,%1,%2,%3,%4,%5,%6,%7}, [%8];"
                 : "=f"(v.r0), "=f"(v.r1), "=f"(v.r2), "=f"(v.r3),
                   "=f"(v.r4), "=f"(v.r5), "=f"(v.r6), "=f"(v.r7)
                 : "l"(p));
    return v;
}

__device__ __forceinline__ float dot8(const F8& a, const F8& w) {
    float t0 = a.r0 * w.r0 + a.r1 * w.r1;
    float t1 = a.r2 * w.r2 + a.r3 * w.r3;
    float t2 = a.r4 * w.r4 + a.r5 * w.r5;
    float t3 = a.r6 * w.r6 + a.r7 * w.r7;
    return (t0 + t1) + (t2 + t3);
}

__global__ __launch_bounds__(256) void attn_gate_kernel(
    const float* __restrict__ xatt,
    const float* __restrict__ xsaut,
    const float* __restrict__ W_act,
    const float* __restrict__ b_act,
    const float* __restrict__ W_saut,
    const float* __restrict__ b_saut,
    const float* __restrict__ W2,
    const float* __restrict__ b2,
    float* __restrict__ out,
    int n_pairs)
{
    const int gtid  = blockIdx.x * blockDim.x + threadIdx.x;
    const int pair  = gtid >> 3;           // 8 lanes per position-pair
    const int lane8 = gtid & 7;
    if (pair >= n_pairs) return;

    const F8 wa = ldg256(W_act  + lane8 * 8);
    const F8 ws = ldg256(W_saut + lane8 * 8);

    // Two adjacent positions: rows at pair*128 and pair*128 + 64 floats.
    const float* pa_base = xatt  + (size_t)pair * 128 + lane8 * 8;
    const float* ps_base = xsaut + (size_t)pair * 128 + lane8 * 8;

    // 4 independent 256-bit loads, front-batched
    const F8 a0 = ldg256(pa_base);
    const F8 a1 = ldg256(pa_base + 64);
    const F8 s0 = ldg256(ps_base);
    const F8 s1 = ldg256(ps_base + 64);

    float pa0 = dot8(a0, wa);
    float pa1 = dot8(a1, wa);
    float ps0 = dot8(s0, ws);
    float ps1 = dot8(s1, ws);

    // Reduce over the 8-lane group (offsets < 8 stay inside the group)
    #pragma unroll
    for (int off = 4; off > 0; off >>= 1) {
        pa0 += __shfl_xor_sync(0xFFFFFFFFu, pa0, off);
        ps0 += __shfl_xor_sync(0xFFFFFFFFu, ps0, off);
        pa1 += __shfl_xor_sync(0xFFFFFFFFu, pa1, off);
        ps1 += __shfl_xor_sync(0xFFFFFFFFu, ps1, off);
    }

    if (lane8 == 0) {
        const float ba = __ldg(b_act);
        const float bs = __ldg(b_saut);
        const float w2 = __ldg(W2);
        const float bb = __ldg(b2);

        float2 o;
        {
            const float xs = ps0 + bs;
            float h = (pa0 + ba) + xs;
            h = (h >= 0.0f) ? h : NEG_SLOPE * h;
            o.x = xs / (1.0f + __expf(-(h * w2 + bb)));
        }
        {
            const float xs = ps1 + bs;
            float h = (pa1 + ba) + xs;
            h = (h >= 0.0f) ? h : NEG_SLOPE * h;
            o.y = xs / (1.0f + __expf(-(h * w2 + bb)));
        }
        reinterpret_cast<float2*>(out)[pair] = o;
    }
}

extern "C" void kernel_launch(void* const* d_in, const int* in_sizes, int n_in,
                              void* d_out, int out_size)
{
    const float* xatt   = (const float*)d_in[0];
    const float* xsaut  = (const float*)d_in[1];
    const float* W_act  = (const float*)d_in[2];
    const float* b_act  = (const float*)d_in[3];
    const float* W_saut = (const float*)d_in[4];
    const float* b_saut = (const float*)d_in[5];
    const float* W2     = (const float*)d_in[6];
    const float* b2     = (const float*)d_in[7];
    float* out = (float*)d_out;

    const int n_pairs = out_size / 2;        // 524,288
    const int threads = 256;
    const long long total_threads = (long long)n_pairs * 8;
    const int blocks = (int)((total_threads + threads - 1) / threads);

    attn_gate_kernel<<<blocks, threads>>>(xatt, xsaut, W_act, b_act,
                                          W_saut, b_saut, W2, b2,
                                          out, n_pairs);
}

// round 7
// speedup vs baseline: 1.0207x; 1.0207x over previous
#include <cuda_runtime.h>

// AttentionBlock fused gate kernel — ILP=4 over FOUR quarter-offset streams.
// Inputs: xatt[B*L*C], xsaut[B*L*C], W_act[C], b_act[1], W_saut[C], b_saut[1], W2[1], b2[1]
// Output: out[B*L] fp32.  B=64, L=16384, C=64 -> n_pos = 1,048,576 (q = 262,144).
//
// 16 lanes handle positions (k, k+q, k+2q, k+3q): 8 front-batched independent
// LDG.128 per thread AND 8 separate sequential address streams across the grid
// (2 tensors x 4 offsets), which measured the highest DRAM utilization in the
// split-stream experiments.

#define NEG_SLOPE 0.3f

__global__ __launch_bounds__(256) void attn_gate_kernel(
    const float* __restrict__ xatt,
    const float* __restrict__ xsaut,
    const float* __restrict__ W_act,
    const float* __restrict__ b_act,
    const float* __restrict__ W_saut,
    const float* __restrict__ b_saut,
    const float* __restrict__ W2,
    const float* __restrict__ b2,
    float* __restrict__ out,
    int q)                                  // n_pos / 4
{
    const int gtid   = blockIdx.x * blockDim.x + threadIdx.x;
    const int k      = gtid >> 4;           // 16 lanes per position group
    const int lane16 = gtid & 15;
    if (k >= q) return;

    const float4 wa = __ldg(reinterpret_cast<const float4*>(W_act)  + lane16);
    const float4 ws = __ldg(reinterpret_cast<const float4*>(W_saut) + lane16);

    const float4* __restrict__ xa4 = reinterpret_cast<const float4*>(xatt);
    const float4* __restrict__ xs4 = reinterpret_cast<const float4*>(xsaut);

    const size_t b0 = (size_t)k * 16 + lane16;
    const size_t stream = (size_t)q * 16;

    // 8 independent global loads, front-batched (MLP=8), 8 address streams
    const float4 a0 = __ldg(xa4 + b0);
    const float4 a1 = __ldg(xa4 + b0 + stream);
    const float4 a2 = __ldg(xa4 + b0 + 2 * stream);
    const float4 a3 = __ldg(xa4 + b0 + 3 * stream);
    const float4 s0 = __ldg(xs4 + b0);
    const float4 s1 = __ldg(xs4 + b0 + stream);
    const float4 s2 = __ldg(xs4 + b0 + 2 * stream);
    const float4 s3 = __ldg(xs4 + b0 + 3 * stream);

    float pa0 = a0.x * wa.x + a0.y * wa.y + a0.z * wa.z + a0.w * wa.w;
    float pa1 = a1.x * wa.x + a1.y * wa.y + a1.z * wa.z + a1.w * wa.w;
    float pa2 = a2.x * wa.x + a2.y * wa.y + a2.z * wa.z + a2.w * wa.w;
    float pa3 = a3.x * wa.x + a3.y * wa.y + a3.z * wa.z + a3.w * wa.w;
    float ps0 = s0.x * ws.x + s0.y * ws.y + s0.z * ws.z + s0.w * ws.w;
    float ps1 = s1.x * ws.x + s1.y * ws.y + s1.z * ws.z + s1.w * ws.w;
    float ps2 = s2.x * ws.x + s2.y * ws.y + s2.z * ws.z + s2.w * ws.w;
    float ps3 = s3.x * ws.x + s3.y * ws.y + s3.z * ws.z + s3.w * ws.w;

    #pragma unroll
    for (int off = 8; off > 0; off >>= 1) {
        pa0 += __shfl_xor_sync(0xFFFFFFFFu, pa0, off);
        ps0 += __shfl_xor_sync(0xFFFFFFFFu, ps0, off);
        pa1 += __shfl_xor_sync(0xFFFFFFFFu, pa1, off);
        ps1 += __shfl_xor_sync(0xFFFFFFFFu, ps1, off);
        pa2 += __shfl_xor_sync(0xFFFFFFFFu, pa2, off);
        ps2 += __shfl_xor_sync(0xFFFFFFFFu, ps2, off);
        pa3 += __shfl_xor_sync(0xFFFFFFFFu, pa3, off);
        ps3 += __shfl_xor_sync(0xFFFFFFFFu, ps3, off);
    }

    if (lane16 == 0) {
        const float ba = __ldg(b_act);
        const float bs = __ldg(b_saut);
        const float w2 = __ldg(W2);
        const float bb = __ldg(b2);

        {
            const float xs = ps0 + bs;
            float h = (pa0 + ba) + xs;
            h = (h >= 0.0f) ? h : NEG_SLOPE * h;
            out[k] = xs / (1.0f + __expf(-(h * w2 + bb)));
        }
        {
            const float xs = ps1 + bs;
            float h = (pa1 + ba) + xs;
            h = (h >= 0.0f) ? h : NEG_SLOPE * h;
            out[k + q] = xs / (1.0f + __expf(-(h * w2 + bb)));
        }
        {
            const float xs = ps2 + bs;
            float h = (pa2 + ba) + xs;
            h = (h >= 0.0f) ? h : NEG_SLOPE * h;
            out[k + 2 * q] = xs / (1.0f + __expf(-(h * w2 + bb)));
        }
        {
            const float xs = ps3 + bs;
            float h = (pa3 + ba) + xs;
            h = (h >= 0.0f) ? h : NEG_SLOPE * h;
            out[k + 3 * q] = xs / (1.0f + __expf(-(h * w2 + bb)));
        }
    }
}

extern "C" void kernel_launch(void* const* d_in, const int* in_sizes, int n_in,
                              void* d_out, int out_size)
{
    const float* xatt   = (const float*)d_in[0];
    const float* xsaut  = (const float*)d_in[1];
    const float* W_act  = (const float*)d_in[2];
    const float* b_act  = (const float*)d_in[3];
    const float* W_saut = (const float*)d_in[4];
    const float* b_saut = (const float*)d_in[5];
    const float* W2     = (const float*)d_in[6];
    const float* b2     = (const float*)d_in[7];
    float* out = (float*)d_out;

    const int q = out_size / 4;              // 262,144
    const int threads = 256;
    const long long total_threads = (long long)q * 16;
    const int blocks = (int)((total_threads + threads - 1) / threads);

    attn_gate_kernel<<<blocks, threads>>>(xatt, xsaut, W_act, b_act,
                                          W_saut, b_saut, W2, b2,
                                          out, q);
}